// round 1
// baseline (speedup 1.0000x reference)
#include <cuda_runtime.h>
#include <cstdint>

// Problem dims
#define BB 64
#define RR 50
#define LL 15
#define DD 1024
#define FF 4096

// GEMM: M=B*R=3200, N=D=1024, K=F=4096
#define GM 3200
#define GN 1024
#define GK 4096

// Tiling
#define BM 128
#define BN 128
#define BK 32
#define BKP (BK + 4)      // padded row length (floats) to avoid bank conflicts
#define NWARPS 8          // 2 (m) x 4 (n)
#define NTHREADS 256

__device__ __forceinline__ uint32_t f2tf32(float x) {
    uint32_t y;
    asm volatile("cvt.rna.tf32.f32 %0, %1;" : "=r"(y) : "f"(x));
    return y;
}

// D(16x8) += A(16x8) * B(8x8), tf32 inputs, f32 accum
__device__ __forceinline__ void mma_tf32(float& c0, float& c1, float& c2, float& c3,
                                         uint32_t a0, uint32_t a1, uint32_t a2, uint32_t a3,
                                         uint32_t b0, uint32_t b1) {
    asm volatile(
        "mma.sync.aligned.m16n8k8.row.col.f32.tf32.tf32.f32 "
        "{%0,%1,%2,%3}, {%4,%5,%6,%7}, {%8,%9}, {%0,%1,%2,%3};\n"
        : "+f"(c0), "+f"(c1), "+f"(c2), "+f"(c3)
        : "r"(a0), "r"(a1), "r"(a2), "r"(a3), "r"(b0), "r"(b1));
}

// vis = relu(features @ W^T + b), written into out[:, 0:1024] of the [3200, 2048] output.
__global__ __launch_bounds__(NTHREADS, 1)
void gemm_relu_kernel(const float* __restrict__ A,   // [GM, GK] features
                      const float* __restrict__ W,   // [GN, GK] weight (K-major)
                      const float* __restrict__ bias,// [GN]
                      float* __restrict__ out)       // [GM, 2*GN]
{
    __shared__ uint32_t As[BM][BKP];
    __shared__ uint32_t Bs[BN][BKP];

    const int tid    = threadIdx.x;
    const int warp   = tid >> 5;
    const int lane   = tid & 31;
    const int warp_m = warp & 1;   // 0..1 -> 64-row slab
    const int warp_n = warp >> 1;  // 0..3 -> 32-col slab

    const int bm = blockIdx.y;     // 0..24
    const int bn = blockIdx.x;     // 0..7
    const int m0 = bm * BM;
    const int n0 = bn * BN;

    // accumulators: 4 (m tiles) x 4 (n tiles) x 4 regs
    float acc[4][4][4];
#pragma unroll
    for (int i = 0; i < 4; i++)
#pragma unroll
        for (int j = 0; j < 4; j++)
#pragma unroll
            for (int r = 0; r < 4; r++) acc[i][j][r] = 0.0f;

    // Global->reg staging: each thread loads 4 float4 for A and 4 for B per k-tile.
    // tile is 128 rows x 32 cols = 128*8 float4 = 1024 float4; 256 threads -> 4 each.
    float4 stA[4], stB[4];

    const int nkt = GK / BK;  // 128

    // prefetch k-tile 0
    {
        const int k0 = 0;
#pragma unroll
        for (int i = 0; i < 4; i++) {
            int idx = tid + i * NTHREADS;        // 0..1023
            int row = idx >> 3;                  // 0..127
            int c4  = idx & 7;                   // 0..7
            stA[i] = *(const float4*)(A + (size_t)(m0 + row) * GK + k0 + c4 * 4);
            stB[i] = *(const float4*)(W + (size_t)(n0 + row) * GK + k0 + c4 * 4);
        }
    }

    for (int kt = 0; kt < nkt; kt++) {
        // commit staged tile to shared (convert to tf32 bits)
#pragma unroll
        for (int i = 0; i < 4; i++) {
            int idx = tid + i * NTHREADS;
            int row = idx >> 3;
            int c   = (idx & 7) * 4;
            As[row][c + 0] = f2tf32(stA[i].x);
            As[row][c + 1] = f2tf32(stA[i].y);
            As[row][c + 2] = f2tf32(stA[i].z);
            As[row][c + 3] = f2tf32(stA[i].w);
            Bs[row][c + 0] = f2tf32(stB[i].x);
            Bs[row][c + 1] = f2tf32(stB[i].y);
            Bs[row][c + 2] = f2tf32(stB[i].z);
            Bs[row][c + 3] = f2tf32(stB[i].w);
        }
        __syncthreads();

        // prefetch next k-tile while computing this one
        if (kt + 1 < nkt) {
            const int k0 = (kt + 1) * BK;
#pragma unroll
            for (int i = 0; i < 4; i++) {
                int idx = tid + i * NTHREADS;
                int row = idx >> 3;
                int c4  = idx & 7;
                stA[i] = *(const float4*)(A + (size_t)(m0 + row) * GK + k0 + c4 * 4);
                stB[i] = *(const float4*)(W + (size_t)(n0 + row) * GK + k0 + c4 * 4);
            }
        }

        // compute: 4 k-steps of 8
#pragma unroll
        for (int ks = 0; ks < 4; ks++) {
            const int kb = ks * 8;
            uint32_t af[4][4];
            uint32_t bf[4][2];
            const int arow = warp_m * 64 + (lane >> 2);
            const int kcol = kb + (lane & 3);
#pragma unroll
            for (int tm = 0; tm < 4; tm++) {
                int r = arow + tm * 16;
                af[tm][0] = As[r][kcol];
                af[tm][1] = As[r + 8][kcol];
                af[tm][2] = As[r][kcol + 4];
                af[tm][3] = As[r + 8][kcol + 4];
            }
            const int bcol = warp_n * 32 + (lane >> 2);
#pragma unroll
            for (int tn = 0; tn < 4; tn++) {
                int c = bcol + tn * 8;
                bf[tn][0] = Bs[c][kb + (lane & 3)];
                bf[tn][1] = Bs[c][kb + 4 + (lane & 3)];
            }
#pragma unroll
            for (int tm = 0; tm < 4; tm++)
#pragma unroll
                for (int tn = 0; tn < 4; tn++)
                    mma_tf32(acc[tm][tn][0], acc[tm][tn][1], acc[tm][tn][2], acc[tm][tn][3],
                             af[tm][0], af[tm][1], af[tm][2], af[tm][3],
                             bf[tn][0], bf[tn][1]);
        }
        __syncthreads();
    }

    // Epilogue: bias + relu, store into out[:, 0:1024] (row stride 2048)
#pragma unroll
    for (int tn = 0; tn < 4; tn++) {
        int n = n0 + warp_n * 32 + tn * 8 + (lane & 3) * 2;
        float b0 = __ldg(bias + n);
        float b1 = __ldg(bias + n + 1);
#pragma unroll
        for (int tm = 0; tm < 4; tm++) {
            int r0 = m0 + warp_m * 64 + tm * 16 + (lane >> 2);
            float v0 = fmaxf(acc[tm][tn][0] + b0, 0.0f);
            float v1 = fmaxf(acc[tm][tn][1] + b1, 0.0f);
            float v2 = fmaxf(acc[tm][tn][2] + b0, 0.0f);
            float v3 = fmaxf(acc[tm][tn][3] + b1, 0.0f);
            *(float2*)(out + (size_t)r0 * (2 * GN) + n)       = make_float2(v0, v1);
            *(float2*)(out + (size_t)(r0 + 8) * (2 * GN) + n) = make_float2(v2, v3);
        }
    }
}

// mean over phrase tokens -> out[:, 1024:2048]
__global__ __launch_bounds__(256, 8)
void meanpool_kernel(const float* __restrict__ phrases,   // [3200, L, D]
                     const int* __restrict__ lens,        // [3200]
                     float* __restrict__ out)             // [3200, 2048]
{
    const int row = blockIdx.x;          // 0..3199
    const float inv = 1.0f / (float)__ldg(lens + row);
    const int d4 = threadIdx.x;          // 0..255, covers D/4 = 256 float4
    const float4* p = (const float4*)(phrases + (size_t)row * LL * DD);
    float sx = 0.f, sy = 0.f, sz = 0.f, sw = 0.f;
#pragma unroll
    for (int l = 0; l < LL; l++) {
        float4 v = __ldg(p + l * (DD / 4) + d4);
        sx += v.x; sy += v.y; sz += v.z; sw += v.w;
    }
    float4 r = make_float4(sx * inv, sy * inv, sz * inv, sw * inv);
    *((float4*)(out + (size_t)row * (2 * DD) + DD) + d4) = r;
}

extern "C" void kernel_launch(void* const* d_in, const int* in_sizes, int n_in,
                              void* d_out, int out_size) {
    const float* features = (const float*)d_in[0];   // [64,50,4096]
    const float* phrases  = (const float*)d_in[1];   // [64,50,15,1024]
    const float* W        = (const float*)d_in[2];   // [1024,4096]
    const float* bias     = (const float*)d_in[3];   // [1024]
    const int*   lens     = (const int*)d_in[4];     // [64,50]
    float* out = (float*)d_out;                      // [64,50,2048]

    dim3 ggrid(GN / BN, GM / BM);   // (8, 25)
    gemm_relu_kernel<<<ggrid, NTHREADS>>>(features, W, bias, out);
    meanpool_kernel<<<GM, 256>>>(phrases, lens, out);
}

// round 3
// speedup vs baseline: 1.1483x; 1.1483x over previous
#include <cuda_runtime.h>
#include <cstdint>

// Problem dims
#define BB 64
#define RR 50
#define LL 15
#define DD 1024
#define FF 4096

// GEMM: M=B*R=3200, N=D=1024, K=F=4096
#define GM 3200
#define GN 1024
#define GK 4096

// GEMM tiling: CTA tile 128(M) x 256(N) x 32(K); grid = 25 x 4 = 100 CTAs (single wave).
#define BM 128
#define BN 256
#define BK 32
#define AP 36                       // padded K row length in floats (bank-conflict-free)
#define STAGES 4
#define A_STAGE_BYTES (BM * AP * 4)      // 18432
#define B_STAGE_BYTES (BN * AP * 4)      // 36864
#define STAGE_BYTES (A_STAGE_BYTES + B_STAGE_BYTES)  // 55296
#define SMEM_TOTAL (STAGES * STAGE_BYTES)            // 221184
#define NTHREADS 256
#define NIT (GK / BK)               // 128

// tf32-rounded copies of A and W (written by prepass with cvt.rna)
__device__ float g_Atf[GM * GK];    // 52.4 MB
__device__ float g_Wtf[GN * GK];    // 16.8 MB

__device__ __forceinline__ uint32_t f2tf32(float x) {
    uint32_t y;
    asm volatile("cvt.rna.tf32.f32 %0, %1;" : "=r"(y) : "f"(x));
    return y;
}

__device__ __forceinline__ void mma_tf32(float& c0, float& c1, float& c2, float& c3,
                                         uint32_t a0, uint32_t a1, uint32_t a2, uint32_t a3,
                                         uint32_t b0, uint32_t b1) {
    asm volatile(
        "mma.sync.aligned.m16n8k8.row.col.f32.tf32.tf32.f32 "
        "{%0,%1,%2,%3}, {%4,%5,%6,%7}, {%8,%9}, {%0,%1,%2,%3};\n"
        : "+f"(c0), "+f"(c1), "+f"(c2), "+f"(c3)
        : "r"(a0), "r"(a1), "r"(a2), "r"(a3), "r"(b0), "r"(b1));
}

__device__ __forceinline__ uint32_t smem_u32(const void* p) {
    uint32_t a;
    asm("{ .reg .u64 t; cvta.to.shared.u64 t, %1; cvt.u32.u64 %0, t; }" : "=r"(a) : "l"(p));
    return a;
}

#define CP_ASYNC16(dst, src) \
    asm volatile("cp.async.cg.shared.global [%0], [%1], 16;" :: "r"(dst), "l"(src) : "memory")
#define CP_COMMIT() asm volatile("cp.async.commit_group;" ::: "memory")
#define CP_WAIT(n) asm volatile("cp.async.wait_group %0;" :: "n"(n) : "memory")

// ───────────────────────── prepass: fp32 -> tf32(rna) bits ─────────────────────────
__global__ void __launch_bounds__(256)
cvt_tf32_kernel(const float* __restrict__ A, const float* __restrict__ W) {
    const int na4 = GM * GK / 4;
    const int nw4 = GN * GK / 4;
    const int total = na4 + nw4;
    for (int i = blockIdx.x * blockDim.x + threadIdx.x; i < total; i += gridDim.x * blockDim.x) {
        float4 v;
        float4* dst;
        if (i < na4) {
            v = __ldg((const float4*)A + i);
            dst = (float4*)g_Atf + i;
        } else {
            v = __ldg((const float4*)W + (i - na4));
            dst = (float4*)g_Wtf + (i - na4);
        }
        float4 r;
        r.x = __uint_as_float(f2tf32(v.x));
        r.y = __uint_as_float(f2tf32(v.y));
        r.z = __uint_as_float(f2tf32(v.z));
        r.w = __uint_as_float(f2tf32(v.w));
        *dst = r;
    }
}

// ───────────────────────── GEMM: vis = relu(A @ W^T + b) ─────────────────────────
__global__ void __launch_bounds__(NTHREADS, 1)
gemm_relu_kernel(const float* __restrict__ bias, float* __restrict__ out) {
    extern __shared__ char smem[];
    const uint32_t sb = smem_u32(smem);

    const int tid = threadIdx.x;
    const int warp = tid >> 5;      // 0..7
    const int lane = tid & 31;
    const int warp_m = warp & 1;    // 0..1 -> 64-row slab
    const int warp_n = warp >> 1;   // 0..3 -> 64-col slab
    const int m0 = blockIdx.y * BM; // 0..24 * 128
    const int n0 = blockIdx.x * BN; // 0..3 * 256

    // cp.async mappings
    // A tile: 1024 16B-chunks (128 rows x 8); each thread does 4.
    // B tile: 2048 16B-chunks (256 rows x 8); each thread does 8.
    uint32_t a_dst[4], b_dst[8];
    const float* a_src[4];
    const float* b_src[8];
#pragma unroll
    for (int i = 0; i < 4; i++) {
        int id = tid + i * NTHREADS;
        int row = id >> 3, c4 = id & 7;
        a_dst[i] = row * (AP * 4) + c4 * 16;
        a_src[i] = g_Atf + (size_t)(m0 + row) * GK + c4 * 4;
    }
#pragma unroll
    for (int i = 0; i < 8; i++) {
        int id = tid + i * NTHREADS;
        int row = id >> 3, c4 = id & 7;
        b_dst[i] = A_STAGE_BYTES + row * (AP * 4) + c4 * 16;
        b_src[i] = g_Wtf + (size_t)(n0 + row) * GK + c4 * 4;
    }

    float acc[4][8][4];
#pragma unroll
    for (int tm = 0; tm < 4; tm++)
#pragma unroll
        for (int tn = 0; tn < 8; tn++)
#pragma unroll
            for (int r = 0; r < 4; r++) acc[tm][tn][r] = 0.0f;

    // preload stages 0..STAGES-2
#pragma unroll
    for (int s = 0; s < STAGES - 1; s++) {
        const uint32_t st = sb + s * STAGE_BYTES;
        const int k0 = s * BK;
#pragma unroll
        for (int i = 0; i < 4; i++) CP_ASYNC16(st + a_dst[i], a_src[i] + k0);
#pragma unroll
        for (int i = 0; i < 8; i++) CP_ASYNC16(st + b_dst[i], b_src[i] + k0);
        CP_COMMIT();
    }

    for (int it = 0; it < NIT; it++) {
        CP_WAIT(STAGES - 2);
        __syncthreads();

        // issue loads for stage it+STAGES-1 (overwrites stage computed last iter;
        // the __syncthreads above guarantees everyone is done with it)
        {
            const int ld = it + STAGES - 1;
            if (ld < NIT) {
                const uint32_t st = sb + (ld & (STAGES - 1)) * STAGE_BYTES;
                const int k0 = ld * BK;
#pragma unroll
                for (int i = 0; i < 4; i++) CP_ASYNC16(st + a_dst[i], a_src[i] + k0);
#pragma unroll
                for (int i = 0; i < 8; i++) CP_ASYNC16(st + b_dst[i], b_src[i] + k0);
            }
            CP_COMMIT();
        }

        // compute on stage it
        const uint32_t* As = (const uint32_t*)(smem + (it & (STAGES - 1)) * STAGE_BYTES);
        const uint32_t* Bs = (const uint32_t*)(smem + (it & (STAGES - 1)) * STAGE_BYTES + A_STAGE_BYTES);
#pragma unroll
        for (int ks = 0; ks < 4; ks++) {
            const int kc = ks * 8 + (lane & 3);
            uint32_t af[4][4];
#pragma unroll
            for (int tm = 0; tm < 4; tm++) {
                const int r = warp_m * 64 + tm * 16 + (lane >> 2);
                af[tm][0] = As[r * AP + kc];
                af[tm][1] = As[(r + 8) * AP + kc];
                af[tm][2] = As[r * AP + kc + 4];
                af[tm][3] = As[(r + 8) * AP + kc + 4];
            }
            uint32_t bf[8][2];
#pragma unroll
            for (int tn = 0; tn < 8; tn++) {
                const int c = warp_n * 64 + tn * 8 + (lane >> 2);
                bf[tn][0] = Bs[c * AP + kc];
                bf[tn][1] = Bs[c * AP + kc + 4];
            }
#pragma unroll
            for (int tm = 0; tm < 4; tm++)
#pragma unroll
                for (int tn = 0; tn < 8; tn++)
                    mma_tf32(acc[tm][tn][0], acc[tm][tn][1], acc[tm][tn][2], acc[tm][tn][3],
                             af[tm][0], af[tm][1], af[tm][2], af[tm][3],
                             bf[tn][0], bf[tn][1]);
        }
    }

    // epilogue: bias + relu -> out[:, 0:1024] of [3200, 2048]
#pragma unroll
    for (int tn = 0; tn < 8; tn++) {
        const int n = n0 + warp_n * 64 + tn * 8 + (lane & 3) * 2;
        const float b0 = __ldg(bias + n);
        const float b1 = __ldg(bias + n + 1);
#pragma unroll
        for (int tm = 0; tm < 4; tm++) {
            const int r0 = m0 + warp_m * 64 + tm * 16 + (lane >> 2);
            float2 v0, v1;
            v0.x = fmaxf(acc[tm][tn][0] + b0, 0.0f);
            v0.y = fmaxf(acc[tm][tn][1] + b1, 0.0f);
            v1.x = fmaxf(acc[tm][tn][2] + b0, 0.0f);
            v1.y = fmaxf(acc[tm][tn][3] + b1, 0.0f);
            *(float2*)(out + (size_t)r0 * (2 * GN) + n) = v0;
            *(float2*)(out + (size_t)(r0 + 8) * (2 * GN) + n) = v1;
        }
    }
}

// ───────────────────────── mean-pool -> out[:, 1024:2048] ─────────────────────────
__global__ void __launch_bounds__(256, 8)
meanpool_kernel(const float* __restrict__ phrases, const int* __restrict__ lens,
                float* __restrict__ out) {
    const int row = blockIdx.x;
    const float inv = 1.0f / (float)__ldg(lens + row);
    const int d4 = threadIdx.x;
    const float4* p = (const float4*)(phrases + (size_t)row * LL * DD);
    float sx = 0.f, sy = 0.f, sz = 0.f, sw = 0.f;
#pragma unroll
    for (int l = 0; l < LL; l++) {
        float4 v = __ldg(p + l * (DD / 4) + d4);
        sx += v.x; sy += v.y; sz += v.z; sw += v.w;
    }
    float4 r = make_float4(sx * inv, sy * inv, sz * inv, sw * inv);
    *((float4*)(out + (size_t)row * (2 * DD) + DD) + d4) = r;
}

extern "C" void kernel_launch(void* const* d_in, const int* in_sizes, int n_in,
                              void* d_out, int out_size) {
    const float* features = (const float*)d_in[0];
    const float* phrases  = (const float*)d_in[1];
    const float* W        = (const float*)d_in[2];
    const float* bias     = (const float*)d_in[3];
    const int*   lens     = (const int*)d_in[4];
    float* out = (float*)d_out;

    cvt_tf32_kernel<<<2048, 256>>>(features, W);

    cudaFuncSetAttribute(gemm_relu_kernel, cudaFuncAttributeMaxDynamicSharedMemorySize, SMEM_TOTAL);
    dim3 ggrid(GN / BN, GM / BM);  // (4, 25) = 100 CTAs
    gemm_relu_kernel<<<ggrid, NTHREADS, SMEM_TOTAL>>>(bias, out);

    meanpool_kernel<<<GM, 256>>>(phrases, lens, out);
}

// round 4
// speedup vs baseline: 1.2730x; 1.1086x over previous
#include <cuda_runtime.h>
#include <cstdint>

// Problem dims
#define BB 64
#define RR 50
#define LL 15
#define DD 1024
#define FF 4096

// GEMM: M=B*R=3200, N=D=1024, K=F=4096
#define GM 3200
#define GN 1024
#define GK 4096

// GEMM tiling: CTA tile 128x128x32, split-K=2 -> grid (8, 25, 2) = 400 CTAs.
#define BM 128
#define BN 128
#define BK 32
#define KSPLIT 2
#define KHALF (GK / KSPLIT)         // 2048
#define NIT (KHALF / BK)            // 64
#define AP 36                       // padded row stride in words (bank-conflict-free)
#define STAGES 4
#define A_STAGE_BYTES (BM * AP * 4)          // 18432
#define STAGE_BYTES (2 * BM * AP * 4)        // 36864 (A + B)
#define SMEM_TOTAL (STAGES * STAGE_BYTES)    // 147456
#define NTHREADS 256

// tf32(rna)-rounded copies of A and W; split-1 partial scratch
__device__ float g_Atf[GM * GK];
__device__ float g_Wtf[GN * GK];
__device__ float g_part[GM * GN];

__device__ __forceinline__ uint32_t f2tf32(float x) {
    uint32_t y;
    asm volatile("cvt.rna.tf32.f32 %0, %1;" : "=r"(y) : "f"(x));
    return y;
}

__device__ __forceinline__ void mma_tf32(float& c0, float& c1, float& c2, float& c3,
                                         uint32_t a0, uint32_t a1, uint32_t a2, uint32_t a3,
                                         uint32_t b0, uint32_t b1) {
    asm volatile(
        "mma.sync.aligned.m16n8k8.row.col.f32.tf32.tf32.f32 "
        "{%0,%1,%2,%3}, {%4,%5,%6,%7}, {%8,%9}, {%0,%1,%2,%3};\n"
        : "+f"(c0), "+f"(c1), "+f"(c2), "+f"(c3)
        : "r"(a0), "r"(a1), "r"(a2), "r"(a3), "r"(b0), "r"(b1));
}

__device__ __forceinline__ uint32_t smem_u32(const void* p) {
    uint32_t a;
    asm("{ .reg .u64 t; cvta.to.shared.u64 t, %1; cvt.u32.u64 %0, t; }" : "=r"(a) : "l"(p));
    return a;
}

#define CP_ASYNC16(dst, src) \
    asm volatile("cp.async.cg.shared.global [%0], [%1], 16;" :: "r"(dst), "l"(src) : "memory")
#define CP_COMMIT() asm volatile("cp.async.commit_group;" ::: "memory")
#define CP_WAIT(n) asm volatile("cp.async.wait_group %0;" :: "n"(n) : "memory")

#define LDSM4(r0, r1, r2, r3, addr) \
    asm volatile("ldmatrix.sync.aligned.m8n8.x4.shared.b16 {%0,%1,%2,%3}, [%4];" \
                 : "=r"(r0), "=r"(r1), "=r"(r2), "=r"(r3) : "r"(addr))

// ───────────────────────── prepass: fp32 -> tf32(rna) bits ─────────────────────────
__global__ void __launch_bounds__(256)
cvt_tf32_kernel(const float* __restrict__ A, const float* __restrict__ W) {
    const int na4 = GM * GK / 4;
    const int nw4 = GN * GK / 4;
    const int total = na4 + nw4;
    for (int i = blockIdx.x * blockDim.x + threadIdx.x; i < total; i += gridDim.x * blockDim.x) {
        float4 v;
        float4* dst;
        if (i < na4) {
            v = __ldg((const float4*)A + i);
            dst = (float4*)g_Atf + i;
        } else {
            v = __ldg((const float4*)W + (i - na4));
            dst = (float4*)g_Wtf + (i - na4);
        }
        float4 r;
        r.x = __uint_as_float(f2tf32(v.x));
        r.y = __uint_as_float(f2tf32(v.y));
        r.z = __uint_as_float(f2tf32(v.z));
        r.w = __uint_as_float(f2tf32(v.w));
        *dst = r;
    }
}

// ───────────────────── GEMM partials: A @ W^T (tf32), split-K=2 ─────────────────────
__global__ void __launch_bounds__(NTHREADS, 1)
gemm_partial_kernel(float* __restrict__ out) {
    extern __shared__ char smem[];
    const uint32_t sb = smem_u32(smem);

    const int tid = threadIdx.x;
    const int warp = tid >> 5;      // 0..7
    const int lane = tid & 31;
    const int warp_m = warp & 1;    // 0..1 -> 64-row slab
    const int warp_n = warp >> 1;   // 0..3 -> 32-col slab
    const int m0 = blockIdx.y * BM;
    const int n0 = blockIdx.x * BN;
    const int kbase = blockIdx.z * KHALF;

    // cp.async mappings: A tile 128x8 chunks, B tile 128x8 chunks; 4 each per thread
    uint32_t a_dst[4], b_dst[4];
    const float* a_src[4];
    const float* b_src[4];
#pragma unroll
    for (int i = 0; i < 4; i++) {
        int id = tid + i * NTHREADS;     // 0..1023
        int row = id >> 3, c4 = id & 7;
        a_dst[i] = row * (AP * 4) + c4 * 16;
        b_dst[i] = A_STAGE_BYTES + row * (AP * 4) + c4 * 16;
        a_src[i] = g_Atf + (size_t)(m0 + row) * GK + kbase + c4 * 4;
        b_src[i] = g_Wtf + (size_t)(n0 + row) * GK + kbase + c4 * 4;
    }

    // ldmatrix per-lane base addresses (byte offsets within a stage)
    // A: matrix m = lane>>3: row_off = (m&1)*8, k_off = (m>>1)*4
    const int la_row = (lane & 7) + ((lane >> 3) & 1) * 8;
    const int la_k = (lane >> 4) * 4;
    const uint32_t pA_base = ((warp_m * 64 + la_row) * AP + la_k) * 4;
    // B: matrix m: n_off = (m>>1)*8, k_off = (m&1)*4
    const int lb_row = (lane & 7) + ((lane >> 4) & 1) * 8;
    const int lb_k = ((lane >> 3) & 1) * 4;
    const uint32_t pB_base = A_STAGE_BYTES + ((warp_n * 32 + lb_row) * AP + lb_k) * 4;

    float acc[4][4][4];
#pragma unroll
    for (int tm = 0; tm < 4; tm++)
#pragma unroll
        for (int tn = 0; tn < 4; tn++)
#pragma unroll
            for (int r = 0; r < 4; r++) acc[tm][tn][r] = 0.0f;

    // preload stages 0..STAGES-2
#pragma unroll
    for (int s = 0; s < STAGES - 1; s++) {
        const uint32_t st = sb + s * STAGE_BYTES;
        const int k0 = s * BK;
#pragma unroll
        for (int i = 0; i < 4; i++) {
            CP_ASYNC16(st + a_dst[i], a_src[i] + k0);
            CP_ASYNC16(st + b_dst[i], b_src[i] + k0);
        }
        CP_COMMIT();
    }

    for (int it = 0; it < NIT; it++) {
        CP_WAIT(STAGES - 2);
        __syncthreads();

        // issue loads for stage it+STAGES-1
        {
            const int ld = it + STAGES - 1;
            if (ld < NIT) {
                const uint32_t st = sb + (ld & (STAGES - 1)) * STAGE_BYTES;
                const int k0 = ld * BK;
#pragma unroll
                for (int i = 0; i < 4; i++) {
                    CP_ASYNC16(st + a_dst[i], a_src[i] + k0);
                    CP_ASYNC16(st + b_dst[i], b_src[i] + k0);
                }
            }
            CP_COMMIT();
        }

        const uint32_t st = sb + (it & (STAGES - 1)) * STAGE_BYTES;
        const uint32_t aA = st + pA_base;
        const uint32_t aB = st + pB_base;
#pragma unroll
        for (int ks = 0; ks < 4; ks++) {
            uint32_t af[4][4], bf[4][2];
#pragma unroll
            for (int tm = 0; tm < 4; tm++)
                LDSM4(af[tm][0], af[tm][1], af[tm][2], af[tm][3],
                      aA + (tm * 16 * AP + ks * 8) * 4);
#pragma unroll
            for (int pr = 0; pr < 2; pr++)
                LDSM4(bf[pr * 2][0], bf[pr * 2][1], bf[pr * 2 + 1][0], bf[pr * 2 + 1][1],
                      aB + (pr * 16 * AP + ks * 8) * 4);
#pragma unroll
            for (int tm = 0; tm < 4; tm++)
#pragma unroll
                for (int tn = 0; tn < 4; tn++)
                    mma_tf32(acc[tm][tn][0], acc[tm][tn][1], acc[tm][tn][2], acc[tm][tn][3],
                             af[tm][0], af[tm][1], af[tm][2], af[tm][3],
                             bf[tn][0], bf[tn][1]);
        }
    }

    // write raw partial: split 0 -> out[:, 0:1024] (stride 2048); split 1 -> g_part (stride 1024)
    float* dst = (blockIdx.z == 0) ? out : g_part;
    const int stride = (blockIdx.z == 0) ? (2 * GN) : GN;
#pragma unroll
    for (int tn = 0; tn < 4; tn++) {
        const int n = n0 + warp_n * 32 + tn * 8 + (lane & 3) * 2;
#pragma unroll
        for (int tm = 0; tm < 4; tm++) {
            const int r0 = m0 + warp_m * 64 + tm * 16 + (lane >> 2);
            *(float2*)(dst + (size_t)r0 * stride + n) = make_float2(acc[tm][tn][0], acc[tm][tn][1]);
            *(float2*)(dst + (size_t)(r0 + 8) * stride + n) = make_float2(acc[tm][tn][2], acc[tm][tn][3]);
        }
    }
}

// ─────────────── reduce: out[:,0:1024] = relu(p0 + p1 + bias) ───────────────
__global__ void __launch_bounds__(256)
reduce_kernel(const float* __restrict__ bias, float* __restrict__ out) {
    const int row = blockIdx.x;
    const int t = threadIdx.x;                 // 0..255 -> float4 within 1024 cols
    float4* o = (float4*)(out + (size_t)row * (2 * GN)) + t;
    float4 p0 = *o;
    float4 p1 = __ldg((const float4*)(g_part + (size_t)row * GN) + t);
    float4 bv = __ldg((const float4*)bias + t);
    float4 v;
    v.x = fmaxf(p0.x + p1.x + bv.x, 0.0f);
    v.y = fmaxf(p0.y + p1.y + bv.y, 0.0f);
    v.z = fmaxf(p0.z + p1.z + bv.z, 0.0f);
    v.w = fmaxf(p0.w + p1.w + bv.w, 0.0f);
    *o = v;
}

// ───────────────────────── mean-pool -> out[:, 1024:2048] ─────────────────────────
__global__ void __launch_bounds__(256, 8)
meanpool_kernel(const float* __restrict__ phrases, const int* __restrict__ lens,
                float* __restrict__ out) {
    const int row = blockIdx.x;
    const float inv = 1.0f / (float)__ldg(lens + row);
    const int d4 = threadIdx.x;
    const float4* p = (const float4*)(phrases + (size_t)row * LL * DD);
    float sx = 0.f, sy = 0.f, sz = 0.f, sw = 0.f;
#pragma unroll
    for (int l = 0; l < LL; l++) {
        float4 v = __ldg(p + l * (DD / 4) + d4);
        sx += v.x; sy += v.y; sz += v.z; sw += v.w;
    }
    float4 r = make_float4(sx * inv, sy * inv, sz * inv, sw * inv);
    *((float4*)(out + (size_t)row * (2 * DD) + DD) + d4) = r;
}

extern "C" void kernel_launch(void* const* d_in, const int* in_sizes, int n_in,
                              void* d_out, int out_size) {
    const float* features = (const float*)d_in[0];
    const float* phrases  = (const float*)d_in[1];
    const float* W        = (const float*)d_in[2];
    const float* bias     = (const float*)d_in[3];
    const int*   lens     = (const int*)d_in[4];
    float* out = (float*)d_out;

    cvt_tf32_kernel<<<2048, 256>>>(features, W);

    cudaFuncSetAttribute(gemm_partial_kernel, cudaFuncAttributeMaxDynamicSharedMemorySize,
                         SMEM_TOTAL);
    dim3 ggrid(GN / BN, GM / BM, KSPLIT);  // (8, 25, 2) = 400 CTAs
    gemm_partial_kernel<<<ggrid, NTHREADS, SMEM_TOTAL>>>(out);

    reduce_kernel<<<GM, 256>>>(bias, out);
    meanpool_kernel<<<GM, 256>>>(phrases, lens, out);
}

// round 6
// speedup vs baseline: 2.0986x; 1.6486x over previous
#include <cuda_runtime.h>
#include <cuda_fp16.h>
#include <cstdint>

// Problem dims
#define BB 64
#define RR 50
#define LL 15
#define DD 1024
#define FF 4096

// GEMM: M=B*R=3200, N=D=1024, K=F=4096
#define GM 3200
#define GN 1024
#define GK 4096

// CTA tile 128x128x64 (fp16), split-K=2 -> grid (8, 25, 2) = 400 CTAs.
#define BM 128
#define BN 128
#define BK 64
#define KSPLIT 2
#define KHALF (GK / KSPLIT)         // 2048
#define NIT (KHALF / BK)            // 32
#define APH 72                      // padded row stride in halves (144B, conflict-free)
#define STAGES 4
#define A_STAGE_BYTES (BM * APH * 2)          // 18432
#define STAGE_BYTES (2 * BM * APH * 2)        // 36864 (A + B)
#define SMEM_TOTAL (STAGES * STAGE_BYTES)     // 147456
#define NTHREADS 256

// fp16(rna) copies of A and W; split-1 partial scratch
__device__ __half g_Ah[GM * GK];
__device__ __half g_Wh[GN * GK];
__device__ float g_part[GM * GN];

__device__ __forceinline__ void mma_f16(float& c0, float& c1, float& c2, float& c3,
                                        uint32_t a0, uint32_t a1, uint32_t a2, uint32_t a3,
                                        uint32_t b0, uint32_t b1) {
    asm volatile(
        "mma.sync.aligned.m16n8k16.row.col.f32.f16.f16.f32 "
        "{%0,%1,%2,%3}, {%4,%5,%6,%7}, {%8,%9}, {%0,%1,%2,%3};\n"
        : "+f"(c0), "+f"(c1), "+f"(c2), "+f"(c3)
        : "r"(a0), "r"(a1), "r"(a2), "r"(a3), "r"(b0), "r"(b1));
}

__device__ __forceinline__ uint32_t smem_u32(const void* p) {
    uint32_t a;
    asm("{ .reg .u64 t; cvta.to.shared.u64 t, %1; cvt.u32.u64 %0, t; }" : "=r"(a) : "l"(p));
    return a;
}

#define CP_ASYNC16(dst, src) \
    asm volatile("cp.async.cg.shared.global [%0], [%1], 16;" :: "r"(dst), "l"(src) : "memory")
#define CP_COMMIT() asm volatile("cp.async.commit_group;" ::: "memory")
#define CP_WAIT(n) asm volatile("cp.async.wait_group %0;" :: "n"(n) : "memory")

#define LDSM4(r0, r1, r2, r3, addr) \
    asm volatile("ldmatrix.sync.aligned.m8n8.x4.shared.b16 {%0,%1,%2,%3}, [%4];" \
                 : "=r"(r0), "=r"(r1), "=r"(r2), "=r"(r3) : "r"(addr))

// ─────────────────── prepass: fp32 -> fp16(rna) ───────────────────
__global__ void __launch_bounds__(256)
cvt_f16_kernel(const float* __restrict__ A, const float* __restrict__ W) {
    const int na8 = GM * GK / 8;   // 16B output chunks for A
    const int nw8 = GN * GK / 8;
    const int total = na8 + nw8;
    for (int i = blockIdx.x * blockDim.x + threadIdx.x; i < total; i += gridDim.x * blockDim.x) {
        const float4* src;
        uint4* dst;
        if (i < na8) {
            src = (const float4*)A + (size_t)i * 2;
            dst = (uint4*)g_Ah + i;
        } else {
            src = (const float4*)W + (size_t)(i - na8) * 2;
            dst = (uint4*)g_Wh + (i - na8);
        }
        float4 v0 = __ldg(src);
        float4 v1 = __ldg(src + 1);
        __half2 h0 = __floats2half2_rn(v0.x, v0.y);
        __half2 h1 = __floats2half2_rn(v0.z, v0.w);
        __half2 h2 = __floats2half2_rn(v1.x, v1.y);
        __half2 h3 = __floats2half2_rn(v1.z, v1.w);
        uint4 o4;
        o4.x = *(uint32_t*)&h0;
        o4.y = *(uint32_t*)&h1;
        o4.z = *(uint32_t*)&h2;
        o4.w = *(uint32_t*)&h3;
        *dst = o4;
    }
}

// ───────────── GEMM partials: A @ W^T (fp16 in, fp32 acc), split-K=2 ─────────────
__global__ void __launch_bounds__(NTHREADS, 1)
gemm_partial_kernel(float* __restrict__ out) {
    extern __shared__ char smem[];
    const uint32_t sb = smem_u32(smem);

    const int tid = threadIdx.x;
    const int warp = tid >> 5;      // 0..7
    const int lane = tid & 31;
    const int warp_m = warp & 1;    // 0..1 -> 64-row slab
    const int warp_n = warp >> 1;   // 0..3 -> 32-col slab
    const int m0 = blockIdx.y * BM;
    const int n0 = blockIdx.x * BN;
    const int kbase = blockIdx.z * KHALF;

    // cp.async mappings: tile = 128 rows x 8 16B-chunks (64 halves); 4 chunks/thread each
    uint32_t a_dst[4], b_dst[4];
    const __half* a_src[4];
    const __half* b_src[4];
#pragma unroll
    for (int i = 0; i < 4; i++) {
        int id = tid + i * NTHREADS;     // 0..1023
        int row = id >> 3, c8 = id & 7;
        a_dst[i] = row * (APH * 2) + c8 * 16;
        b_dst[i] = A_STAGE_BYTES + row * (APH * 2) + c8 * 16;
        a_src[i] = g_Ah + (size_t)(m0 + row) * GK + kbase + c8 * 8;
        b_src[i] = g_Wh + (size_t)(n0 + row) * GK + kbase + c8 * 8;
    }

    // ldmatrix lane bases (byte offsets within a stage)
    const int la_row = (lane & 7) + ((lane >> 3) & 1) * 8;
    const uint32_t pA_base = ((warp_m * 64 + la_row) * APH + (lane >> 4) * 8) * 2;
    const int lb_row = (lane & 7) + ((lane >> 4) & 1) * 8;
    const uint32_t pB_base =
        A_STAGE_BYTES + ((warp_n * 32 + lb_row) * APH + ((lane >> 3) & 1) * 8) * 2;

    float acc[4][4][4];
#pragma unroll
    for (int tm = 0; tm < 4; tm++)
#pragma unroll
        for (int tn = 0; tn < 4; tn++)
#pragma unroll
            for (int r = 0; r < 4; r++) acc[tm][tn][r] = 0.0f;

    // preload stages 0..STAGES-2
#pragma unroll
    for (int s = 0; s < STAGES - 1; s++) {
        const uint32_t st = sb + s * STAGE_BYTES;
        const int k0 = s * BK;
#pragma unroll
        for (int i = 0; i < 4; i++) {
            CP_ASYNC16(st + a_dst[i], a_src[i] + k0);
            CP_ASYNC16(st + b_dst[i], b_src[i] + k0);
        }
        CP_COMMIT();
    }

    uint32_t af[2][4][4], bf[2][4][2];

    for (int it = 0; it < NIT; it++) {
        CP_WAIT(STAGES - 2);
        __syncthreads();

        // issue loads for stage it+STAGES-1
        {
            const int ld = it + STAGES - 1;
            if (ld < NIT) {
                const uint32_t st = sb + (ld & (STAGES - 1)) * STAGE_BYTES;
                const int k0 = ld * BK;
#pragma unroll
                for (int i = 0; i < 4; i++) {
                    CP_ASYNC16(st + a_dst[i], a_src[i] + k0);
                    CP_ASYNC16(st + b_dst[i], b_src[i] + k0);
                }
            }
            CP_COMMIT();
        }

        const uint32_t st = sb + (it & (STAGES - 1)) * STAGE_BYTES;
        const uint32_t aA = st + pA_base;
        const uint32_t aB = st + pB_base;

        // prefetch fragments for ks=0
#pragma unroll
        for (int tm = 0; tm < 4; tm++)
            LDSM4(af[0][tm][0], af[0][tm][1], af[0][tm][2], af[0][tm][3],
                  aA + (tm * 16 * APH) * 2);
#pragma unroll
        for (int pr = 0; pr < 2; pr++)
            LDSM4(bf[0][pr * 2][0], bf[0][pr * 2][1], bf[0][pr * 2 + 1][0], bf[0][pr * 2 + 1][1],
                  aB + (pr * 16 * APH) * 2);

        // 4 k16-steps, register double-buffered
#pragma unroll
        for (int ks = 0; ks < 4; ks++) {
            const int cur = ks & 1, nxt = cur ^ 1;
            if (ks < 3) {
                const uint32_t ko = (ks + 1) * 32;  // 16 halves = 32 bytes
#pragma unroll
                for (int tm = 0; tm < 4; tm++)
                    LDSM4(af[nxt][tm][0], af[nxt][tm][1], af[nxt][tm][2], af[nxt][tm][3],
                          aA + (tm * 16 * APH) * 2 + ko);
#pragma unroll
                for (int pr = 0; pr < 2; pr++)
                    LDSM4(bf[nxt][pr * 2][0], bf[nxt][pr * 2][1],
                          bf[nxt][pr * 2 + 1][0], bf[nxt][pr * 2 + 1][1],
                          aB + (pr * 16 * APH) * 2 + ko);
            }
#pragma unroll
            for (int tm = 0; tm < 4; tm++)
#pragma unroll
                for (int tn = 0; tn < 4; tn++)
                    mma_f16(acc[tm][tn][0], acc[tm][tn][1], acc[tm][tn][2], acc[tm][tn][3],
                            af[cur][tm][0], af[cur][tm][1], af[cur][tm][2], af[cur][tm][3],
                            bf[cur][tn][0], bf[cur][tn][1]);
        }
    }

    // write raw partial: split 0 -> out[:, 0:1024] (stride 2048); split 1 -> g_part
    float* dst = (blockIdx.z == 0) ? out : g_part;
    const int stride = (blockIdx.z == 0) ? (2 * GN) : GN;
#pragma unroll
    for (int tn = 0; tn < 4; tn++) {
        const int n = n0 + warp_n * 32 + tn * 8 + (lane & 3) * 2;
#pragma unroll
        for (int tm = 0; tm < 4; tm++) {
            const int r0 = m0 + warp_m * 64 + tm * 16 + (lane >> 2);
            *(float2*)(dst + (size_t)r0 * stride + n) = make_float2(acc[tm][tn][0], acc[tm][tn][1]);
            *(float2*)(dst + (size_t)(r0 + 8) * stride + n) = make_float2(acc[tm][tn][2], acc[tm][tn][3]);
        }
    }
}

// ─────── fused epilogue: out[:,0:1024]=relu(p0+p1+b); out[:,1024:2048]=meanpool ───────
__global__ void __launch_bounds__(256)
epilogue_kernel(const float* __restrict__ bias, const float* __restrict__ phrases,
                const int* __restrict__ lens, float* __restrict__ out) {
    const int row = blockIdx.x;
    const int t = threadIdx.x;   // 0..255 -> one float4 in each half

    // reduce + bias + relu
    float4* o = (float4*)(out + (size_t)row * (2 * GN)) + t;
    float4 p0 = *o;
    float4 p1 = __ldg((const float4*)(g_part + (size_t)row * GN) + t);
    float4 bv = __ldg((const float4*)bias + t);
    float4 v;
    v.x = fmaxf(p0.x + p1.x + bv.x, 0.0f);
    v.y = fmaxf(p0.y + p1.y + bv.y, 0.0f);
    v.z = fmaxf(p0.z + p1.z + bv.z, 0.0f);
    v.w = fmaxf(p0.w + p1.w + bv.w, 0.0f);
    *o = v;

    // mean-pool
    const float inv = 1.0f / (float)__ldg(lens + row);
    const float4* p = (const float4*)(phrases + (size_t)row * LL * DD);
    float sx = 0.f, sy = 0.f, sz = 0.f, sw = 0.f;
#pragma unroll
    for (int l = 0; l < LL; l++) {
        float4 pv = __ldg(p + l * (DD / 4) + t);
        sx += pv.x; sy += pv.y; sz += pv.z; sw += pv.w;
    }
    float4 r = make_float4(sx * inv, sy * inv, sz * inv, sw * inv);
    *((float4*)(out + (size_t)row * (2 * DD) + DD) + t) = r;
}

extern "C" void kernel_launch(void* const* d_in, const int* in_sizes, int n_in,
                              void* d_out, int out_size) {
    const float* features = (const float*)d_in[0];
    const float* phrases  = (const float*)d_in[1];
    const float* W        = (const float*)d_in[2];
    const float* bias     = (const float*)d_in[3];
    const int*   lens     = (const int*)d_in[4];
    float* out = (float*)d_out;

    cvt_f16_kernel<<<2048, 256>>>(features, W);

    cudaFuncSetAttribute(gemm_partial_kernel, cudaFuncAttributeMaxDynamicSharedMemorySize,
                         SMEM_TOTAL);
    dim3 ggrid(GN / BN, GM / BM, KSPLIT);  // (8, 25, 2) = 400 CTAs
    gemm_partial_kernel<<<ggrid, NTHREADS, SMEM_TOTAL>>>(out);

    epilogue_kernel<<<GM, 256>>>(bias, phrases, lens, out);
}

// round 7
// speedup vs baseline: 2.3793x; 1.1337x over previous
#include <cuda_runtime.h>
#include <cuda_fp16.h>
#include <cstdint>

// Problem dims
#define BB 64
#define RR 50
#define LL 15
#define DD 1024
#define FF 4096

// GEMM: M=B*R=3200, N=D=1024, K=F=4096
#define GM 3200
#define GN 1024
#define GK 4096

// CTA tile 128x128x64 (fp16), split-K=2 -> grid (8, 25, 2) = 400 CTAs.
#define BM 128
#define BN 128
#define BK 64
#define KSPLIT 2
#define KHALF (GK / KSPLIT)         // 2048
#define NIT (KHALF / BK)            // 32
#define APH 72                      // padded row stride in halves (144B, conflict-free)
#define STAGES 4
#define A_STAGE_BYTES (BM * APH * 2)          // 18432
#define STAGE_BYTES (2 * BM * APH * 2)        // 36864 (A + B)
#define SMEM_TOTAL (STAGES * STAGE_BYTES)     // 147456
#define NTHREADS 256

// pooling fused into GEMM: 400 CTAs x 8 rows, 120 row-steps, 4 per iteration
#define PROWS 8
#define PSTEPS (PROWS * LL)          // 120
#define PGROUP 4

// fp16(rna) copies of A and W; split-1 partial scratch; 1/len
__device__ __half g_Ah[GM * GK];
__device__ __half g_Wh[GN * GK];
__device__ float g_part[GM * GN];
__device__ float g_invlen[GM];

__device__ __forceinline__ void mma_f16(float& c0, float& c1, float& c2, float& c3,
                                        uint32_t a0, uint32_t a1, uint32_t a2, uint32_t a3,
                                        uint32_t b0, uint32_t b1) {
    asm volatile(
        "mma.sync.aligned.m16n8k16.row.col.f32.f16.f16.f32 "
        "{%0,%1,%2,%3}, {%4,%5,%6,%7}, {%8,%9}, {%0,%1,%2,%3};\n"
        : "+f"(c0), "+f"(c1), "+f"(c2), "+f"(c3)
        : "r"(a0), "r"(a1), "r"(a2), "r"(a3), "r"(b0), "r"(b1));
}

__device__ __forceinline__ uint32_t smem_u32(const void* p) {
    uint32_t a;
    asm("{ .reg .u64 t; cvta.to.shared.u64 t, %1; cvt.u32.u64 %0, t; }" : "=r"(a) : "l"(p));
    return a;
}

#define CP_ASYNC16(dst, src) \
    asm volatile("cp.async.cg.shared.global [%0], [%1], 16;" :: "r"(dst), "l"(src) : "memory")
#define CP_COMMIT() asm volatile("cp.async.commit_group;" ::: "memory")
#define CP_WAIT(n) asm volatile("cp.async.wait_group %0;" :: "n"(n) : "memory")

#define LDSM4(r0, r1, r2, r3, addr) \
    asm volatile("ldmatrix.sync.aligned.m8n8.x4.shared.b16 {%0,%1,%2,%3}, [%4];" \
                 : "=r"(r0), "=r"(r1), "=r"(r2), "=r"(r3) : "r"(addr))

// ─────────────────── prepass: fp32 -> fp16(rna), plus 1/len ───────────────────
__global__ void __launch_bounds__(256)
cvt_f16_kernel(const float* __restrict__ A, const float* __restrict__ W,
               const int* __restrict__ lens) {
    const int gid = blockIdx.x * blockDim.x + threadIdx.x;
    if (gid < GM) g_invlen[gid] = 1.0f / (float)__ldg(lens + gid);

    const int na8 = GM * GK / 8;   // 16B output chunks for A
    const int nw8 = GN * GK / 8;
    const int total = na8 + nw8;
    for (int i = gid; i < total; i += gridDim.x * blockDim.x) {
        const float4* src;
        uint4* dst;
        if (i < na8) {
            src = (const float4*)A + (size_t)i * 2;
            dst = (uint4*)g_Ah + i;
        } else {
            src = (const float4*)W + (size_t)(i - na8) * 2;
            dst = (uint4*)g_Wh + (i - na8);
        }
        float4 v0 = __ldg(src);
        float4 v1 = __ldg(src + 1);
        __half2 h0 = __floats2half2_rn(v0.x, v0.y);
        __half2 h1 = __floats2half2_rn(v0.z, v0.w);
        __half2 h2 = __floats2half2_rn(v1.x, v1.y);
        __half2 h3 = __floats2half2_rn(v1.z, v1.w);
        uint4 o4;
        o4.x = *(uint32_t*)&h0;
        o4.y = *(uint32_t*)&h1;
        o4.z = *(uint32_t*)&h2;
        o4.w = *(uint32_t*)&h3;
        *dst = o4;
    }
}

// ───── GEMM partials (fp16 in, fp32 acc), split-K=2, with fused mean-pool ─────
__global__ void __launch_bounds__(NTHREADS, 1)
gemm_partial_kernel(const float* __restrict__ phrases, float* __restrict__ out) {
    extern __shared__ char smem[];
    const uint32_t sb = smem_u32(smem);

    const int tid = threadIdx.x;
    const int warp = tid >> 5;      // 0..7
    const int lane = tid & 31;
    const int warp_m = warp & 1;    // 0..1 -> 64-row slab
    const int warp_n = warp >> 1;   // 0..3 -> 32-col slab
    const int m0 = blockIdx.y * BM;
    const int n0 = blockIdx.x * BN;
    const int kbase = blockIdx.z * KHALF;

    // pooling assignment: CTA linear id -> 8 phrase rows
    const int cid = blockIdx.z * (GN / BN) * (GM / BM) + blockIdx.y * (GN / BN) + blockIdx.x;
    const int prow0 = cid * PROWS;
    const float4* pf = (const float4*)(phrases + (size_t)prow0 * LL * DD) + tid;

    // cp.async mappings: tile = 128 rows x 8 16B-chunks (64 halves); 4 chunks/thread each
    uint32_t a_dst[4], b_dst[4];
    const __half* a_src[4];
    const __half* b_src[4];
#pragma unroll
    for (int i = 0; i < 4; i++) {
        int id = tid + i * NTHREADS;     // 0..1023
        int row = id >> 3, c8 = id & 7;
        a_dst[i] = row * (APH * 2) + c8 * 16;
        b_dst[i] = A_STAGE_BYTES + row * (APH * 2) + c8 * 16;
        a_src[i] = g_Ah + (size_t)(m0 + row) * GK + kbase + c8 * 8;
        b_src[i] = g_Wh + (size_t)(n0 + row) * GK + kbase + c8 * 8;
    }

    // ldmatrix lane bases (byte offsets within a stage)
    const int la_row = (lane & 7) + ((lane >> 3) & 1) * 8;
    const uint32_t pA_base = ((warp_m * 64 + la_row) * APH + (lane >> 4) * 8) * 2;
    const int lb_row = (lane & 7) + ((lane >> 4) & 1) * 8;
    const uint32_t pB_base =
        A_STAGE_BYTES + ((warp_n * 32 + lb_row) * APH + ((lane >> 3) & 1) * 8) * 2;

    float acc[4][4][4];
#pragma unroll
    for (int tm = 0; tm < 4; tm++)
#pragma unroll
        for (int tn = 0; tn < 4; tn++)
#pragma unroll
            for (int r = 0; r < 4; r++) acc[tm][tn][r] = 0.0f;

    // preload stages 0..STAGES-2
#pragma unroll
    for (int s = 0; s < STAGES - 1; s++) {
        const uint32_t st = sb + s * STAGE_BYTES;
        const int k0 = s * BK;
#pragma unroll
        for (int i = 0; i < 4; i++) {
            CP_ASYNC16(st + a_dst[i], a_src[i] + k0);
            CP_ASYNC16(st + b_dst[i], b_src[i] + k0);
        }
        CP_COMMIT();
    }

    // pool state: prefetch group 0 (steps 0..3)
    float4 pbuf[PGROUP];
#pragma unroll
    for (int j = 0; j < PGROUP; j++) pbuf[j] = __ldg(pf + j * (DD / 4));
    float pacc0 = 0.f, pacc1 = 0.f, pacc2 = 0.f, pacc3 = 0.f;
    float pinv = 0.f;
    int parow = 0, ppl = 0;

    uint32_t af[2][4][4], bf[2][4][2];

    for (int it = 0; it < NIT; it++) {
        CP_WAIT(STAGES - 2);
        __syncthreads();

        // issue loads for stage it+STAGES-1
        {
            const int ld = it + STAGES - 1;
            if (ld < NIT) {
                const uint32_t st = sb + (ld & (STAGES - 1)) * STAGE_BYTES;
                const int k0 = ld * BK;
#pragma unroll
                for (int i = 0; i < 4; i++) {
                    CP_ASYNC16(st + a_dst[i], a_src[i] + k0);
                    CP_ASYNC16(st + b_dst[i], b_src[i] + k0);
                }
            }
            CP_COMMIT();
        }

        // ── fused pooling: accumulate group `it` (already in pbuf), then prefetch it+1 ──
        if (it * PGROUP < PSTEPS) {
#pragma unroll
            for (int j = 0; j < PGROUP; j++) {
                if (ppl == 0) pinv = __ldg(g_invlen + prow0 + parow);
                pacc0 += pbuf[j].x; pacc1 += pbuf[j].y;
                pacc2 += pbuf[j].z; pacc3 += pbuf[j].w;
                ppl++;
                if (ppl == LL) {
                    float4 r = make_float4(pacc0 * pinv, pacc1 * pinv, pacc2 * pinv, pacc3 * pinv);
                    *((float4*)(out + (size_t)(prow0 + parow) * (2 * GN) + GN) + tid) = r;
                    pacc0 = pacc1 = pacc2 = pacc3 = 0.f;
                    ppl = 0;
                    parow++;
                }
            }
            const int sbase = (it + 1) * PGROUP;
            if (sbase < PSTEPS) {
#pragma unroll
                for (int j = 0; j < PGROUP; j++)
                    pbuf[j] = __ldg(pf + (sbase + j) * (DD / 4));
            }
        }

        const uint32_t st = sb + (it & (STAGES - 1)) * STAGE_BYTES;
        const uint32_t aA = st + pA_base;
        const uint32_t aB = st + pB_base;

        // prefetch fragments for ks=0
#pragma unroll
        for (int tm = 0; tm < 4; tm++)
            LDSM4(af[0][tm][0], af[0][tm][1], af[0][tm][2], af[0][tm][3],
                  aA + (tm * 16 * APH) * 2);
#pragma unroll
        for (int pr = 0; pr < 2; pr++)
            LDSM4(bf[0][pr * 2][0], bf[0][pr * 2][1], bf[0][pr * 2 + 1][0], bf[0][pr * 2 + 1][1],
                  aB + (pr * 16 * APH) * 2);

        // 4 k16-steps, register double-buffered
#pragma unroll
        for (int ks = 0; ks < 4; ks++) {
            const int cur = ks & 1, nxt = cur ^ 1;
            if (ks < 3) {
                const uint32_t ko = (ks + 1) * 32;  // 16 halves = 32 bytes
#pragma unroll
                for (int tm = 0; tm < 4; tm++)
                    LDSM4(af[nxt][tm][0], af[nxt][tm][1], af[nxt][tm][2], af[nxt][tm][3],
                          aA + (tm * 16 * APH) * 2 + ko);
#pragma unroll
                for (int pr = 0; pr < 2; pr++)
                    LDSM4(bf[nxt][pr * 2][0], bf[nxt][pr * 2][1],
                          bf[nxt][pr * 2 + 1][0], bf[nxt][pr * 2 + 1][1],
                          aB + (pr * 16 * APH) * 2 + ko);
            }
#pragma unroll
            for (int tm = 0; tm < 4; tm++)
#pragma unroll
                for (int tn = 0; tn < 4; tn++)
                    mma_f16(acc[tm][tn][0], acc[tm][tn][1], acc[tm][tn][2], acc[tm][tn][3],
                            af[cur][tm][0], af[cur][tm][1], af[cur][tm][2], af[cur][tm][3],
                            bf[cur][tn][0], bf[cur][tn][1]);
        }
    }

    // write raw partial: split 0 -> out[:, 0:1024] (stride 2048); split 1 -> g_part
    float* dst = (blockIdx.z == 0) ? out : g_part;
    const int stride = (blockIdx.z == 0) ? (2 * GN) : GN;
#pragma unroll
    for (int tn = 0; tn < 4; tn++) {
        const int n = n0 + warp_n * 32 + tn * 8 + (lane & 3) * 2;
#pragma unroll
        for (int tm = 0; tm < 4; tm++) {
            const int r0 = m0 + warp_m * 64 + tm * 16 + (lane >> 2);
            *(float2*)(dst + (size_t)r0 * stride + n) = make_float2(acc[tm][tn][0], acc[tm][tn][1]);
            *(float2*)(dst + (size_t)(r0 + 8) * stride + n) = make_float2(acc[tm][tn][2], acc[tm][tn][3]);
        }
    }
}

// ─────────────── reduce: out[:,0:1024] = relu(p0 + p1 + bias) ───────────────
__global__ void __launch_bounds__(256)
reduce_kernel(const float* __restrict__ bias, float* __restrict__ out) {
    const int row = blockIdx.x;
    const int t = threadIdx.x;                 // 0..255 -> float4 within 1024 cols
    float4* o = (float4*)(out + (size_t)row * (2 * GN)) + t;
    float4 p0 = *o;
    float4 p1 = __ldg((const float4*)(g_part + (size_t)row * GN) + t);
    float4 bv = __ldg((const float4*)bias + t);
    float4 v;
    v.x = fmaxf(p0.x + p1.x + bv.x, 0.0f);
    v.y = fmaxf(p0.y + p1.y + bv.y, 0.0f);
    v.z = fmaxf(p0.z + p1.z + bv.z, 0.0f);
    v.w = fmaxf(p0.w + p1.w + bv.w, 0.0f);
    *o = v;
}

extern "C" void kernel_launch(void* const* d_in, const int* in_sizes, int n_in,
                              void* d_out, int out_size) {
    const float* features = (const float*)d_in[0];
    const float* phrases  = (const float*)d_in[1];
    const float* W        = (const float*)d_in[2];
    const float* bias     = (const float*)d_in[3];
    const int*   lens     = (const int*)d_in[4];
    float* out = (float*)d_out;

    cvt_f16_kernel<<<2048, 256>>>(features, W, lens);

    cudaFuncSetAttribute(gemm_partial_kernel, cudaFuncAttributeMaxDynamicSharedMemorySize,
                         SMEM_TOTAL);
    dim3 ggrid(GN / BN, GM / BM, KSPLIT);  // (8, 25, 2) = 400 CTAs
    gemm_partial_kernel<<<ggrid, NTHREADS, SMEM_TOTAL>>>(phrases, out);

    reduce_kernel<<<GM, 256>>>(bias, out);
}